// round 14
// baseline (speedup 1.0000x reference)
#include <cuda_runtime.h>
#include <cuda_fp16.h>
#include <math.h>
#include <stdint.h>

// ---------------------------------------------------------------------------
// B=8, T=10, H=W=64, Cin=1, F=64, 4F=256, k=3x3 SAME.
// Output: [2][2][8][64][64][64] fp32.
// fp16 mma.sync (m16n8k16, fp32 accum) implicit-GEMM conv.
// Per block: M=64 positions (one image row) x N=128 (one channel-half, gates
// interleaved), K=576 as 9 taps. Warp tile 32x32 -> 32 accums -> target
// 4 blocks/SM (64 regs). h/out0 stored fp16 (bit-identical path), A-fill via
// cp.async with zero-fill halo, B frags via LDG.128 pairs from gmem
// (L2-broadcast). Mainloop barrier-free. t=0 exact elementwise init; t=9
// writes h,c straight into d_out.
// ---------------------------------------------------------------------------

#define HW    64
#define FDIM  64
#define C4    256
#define NPIX  4096
#define SEG   2097152            // 8*4096*64

__device__ float  g_xg0[10 * 8 * NPIX * C4];   // gate-minor: [timg][pix][f][4]
__device__ float  g_xg1[10 * 8 * NPIX * C4];
__device__ __half g_out0H[10 * 8 * NPIX * FDIM];
__device__ __half g_hH[2][SEG];
__device__ float  g_c[SEG];
// fp16 fragment-ordered weights, uint4-paired:
// uint4[which(3)][half(2)][s(9)][kf(4)][nw(4)][lane(32)][pair(2)]
__device__ uint4 g_wtH[3 * 18432];

__device__ __forceinline__ float hsig(float x) {
    return fminf(fmaxf(0.2f * x + 0.5f, 0.0f), 1.0f);
}
__device__ __forceinline__ unsigned smem_u32(const void* p) {
    unsigned r;
    asm("{ .reg .u64 t; cvta.to.shared.u64 t, %1; cvt.u32.u64 %0, t; }"
        : "=r"(r) : "l"(p));
    return r;
}
__device__ __forceinline__ void ldm_x4(unsigned* a, unsigned addr) {
    asm volatile("ldmatrix.sync.aligned.m8n8.x4.shared.b16 {%0,%1,%2,%3}, [%4];"
        : "=r"(a[0]), "=r"(a[1]), "=r"(a[2]), "=r"(a[3]) : "r"(addr));
}

#define MMA_F16(c, a, bx, by)                                                  \
    asm volatile("mma.sync.aligned.m16n8k16.row.col.f32.f16.f16.f32 "          \
        "{%0,%1,%2,%3}, {%4,%5,%6,%7}, {%8,%9}, {%0,%1,%2,%3};"                \
        : "+f"(c[0]), "+f"(c[1]), "+f"(c[2]), "+f"(c[3])                       \
        : "r"(a[0]), "r"(a[1]), "r"(a[2]), "r"(a[3]), "r"(bx), "r"(by))

// smem: A fp16x2 words [3][66][36] = 7128 u32 (pos stride 36 words). 28512B.
#define SMEM_BYTES 28672

// ---------------------------------------------------------------------------
// t=0 LSTM step, exact (h_prev=0 -> gates = xg). xg is gate-minor [pix][f][4].
__global__ void lstm_init(const float* __restrict__ xg, float* __restrict__ cbuf,
                          __half* __restrict__ hout, __half* __restrict__ outseq) {
    int i = blockIdx.x * blockDim.x + threadIdx.x;     // float4 index in [pix][64]
    if (i >= SEG / 4) return;
    int f4 = (i & 15) << 2;                             // channel base
    int pixg = i >> 4;                                  // img*4096 + pix
    int img = pixg >> 12;
    const float4* xp = (const float4*)(xg +
        ((size_t)(img * 10) * NPIX + (pixg & 4095)) * 256 + (size_t)f4 * 4);
    float4 cn, hn;
    {
        float4 q0 = xp[0], q1 = xp[1], q2 = xp[2], q3 = xp[3];  // (i,f,g,o) x 4 ch
        cn.x = hsig(q0.x) * tanhf(q0.z);
        cn.y = hsig(q1.x) * tanhf(q1.z);
        cn.z = hsig(q2.x) * tanhf(q2.z);
        cn.w = hsig(q3.x) * tanhf(q3.z);
        hn.x = hsig(q0.w) * tanhf(cn.x);
        hn.y = hsig(q1.w) * tanhf(cn.y);
        hn.z = hsig(q2.w) * tanhf(cn.z);
        hn.w = hsig(q3.w) * tanhf(cn.w);
    }
    *(float4*)(cbuf + (size_t)i * 4) = cn;
    __half2 h01 = __floats2half2_rn(hn.x, hn.y);
    __half2 h23 = __floats2half2_rn(hn.z, hn.w);
    *(__half2*)(hout + (size_t)i * 4)     = h01;
    *(__half2*)(hout + (size_t)i * 4 + 2) = h23;
    if (outseq) {
        __half* op = outseq + ((size_t)(img * 10) * NPIX + (pixg & 4095)) * 64 + f4;
        *(__half2*)(op)     = h01;
        *(__half2*)(op + 2) = h23;
    }
}

// Weights -> fp16 B-fragment order, uint4-paired:
// uint2 j decomposition: inner=j&1, pair=(j>>1)&1, lane=(j>>2)&31, nw=(j>>7)&3,
// kf=(j>>9)&3, s=j>>11; ni = pair*2+inner (= gate), tg=lane&3, gg=lane>>2.
// col = ni*64 + half*32 + nw*8 + gg; k0 = s*64 + kf*16 + 2*tg.
// value = { pack(W[k0][col],W[k0+1][col]), pack(W[k0+8][col],W[k0+9][col]) }.
__global__ void prep_w(const float* __restrict__ w0, const float* __restrict__ w1,
                       const float* __restrict__ w2) {
    int idx = blockIdx.x * 256 + threadIdx.x;      // uint2 index
    if (idx >= 3 * 36864) return;
    int which = idx / 36864;
    int rem   = idx - which * 36864;
    int half = rem / 18432;
    int j    = rem - half * 18432;
    int inner = j & 1;
    int pair  = (j >> 1) & 1;
    int lane  = (j >> 2) & 31;
    int nw    = (j >> 7) & 3;
    int kf    = (j >> 9) & 3;
    int s     = j >> 11;
    int ni = pair * 2 + inner;
    int tg = lane & 3, gg = lane >> 2;
    const float* src = (which == 0) ? w0 : (which == 1) ? w1 : w2;
    int k0  = s * 64 + kf * 16 + 2 * tg;
    int col = ni * 64 + half * 32 + nw * 8 + gg;
    __half2 b0 = __floats2half2_rn(src[(size_t)k0 * 256 + col],
                                   src[(size_t)(k0 + 1) * 256 + col]);
    __half2 b1 = __floats2half2_rn(src[(size_t)(k0 + 8) * 256 + col],
                                   src[(size_t)(k0 + 9) * 256 + col]);
    uint2 v;
    v.x = *(unsigned*)&b0;
    v.y = *(unsigned*)&b1;
    ((uint2*)g_wtH)[idx] = v;
}

// Layer-0 input conv (Cin=1), exact fp32, writes xg gate-minor:
// thread tid = source col (gate*64+f) -> stored at [pix][f*4 + gate].
__global__ void conv_l0(const float* __restrict__ x, const float* __restrict__ w,
                        const float* __restrict__ b, float* __restrict__ xg) {
    __shared__ float ps[18 * 18];
    __shared__ float ws[9 * C4];
    int img = blockIdx.y;
    int by0 = (blockIdx.x >> 2) * 16, bx0 = (blockIdx.x & 3) * 16;
    int tid = threadIdx.x;
    int perm = (tid & 63) * 4 + (tid >> 6);
    for (int i = tid; i < 324; i += 256) {
        int ly = i / 18, lx = i - ly * 18;
        int gy = by0 + ly - 1, gx = bx0 + lx - 1;
        float v = 0.0f;
        if (gy >= 0 && gy < HW && gx >= 0 && gx < HW)
            v = x[(size_t)img * NPIX + gy * HW + gx];
        ps[i] = v;
    }
    for (int i = tid; i < 9 * C4; i += 256) ws[i] = w[i];
    __syncthreads();
    float wr[9];
#pragma unroll
    for (int tp = 0; tp < 9; ++tp) wr[tp] = ws[tp * C4 + tid];
    float bv = b[tid];
    for (int p = 0; p < 256; ++p) {
        int py = p >> 4, px = p & 15;
        float a = bv;
#pragma unroll
        for (int tp = 0; tp < 9; ++tp) {
            int dy = tp / 3, dx = tp - 3 * dy;
            a += ps[(py + dy) * 18 + (px + dx)] * wr[tp];
        }
        xg[((size_t)img * NPIX + (by0 + py) * HW + (bx0 + px)) * C4 + perm] = a;
    }
}

// ---------------------------------------------------------------------------
// fp16 mma.sync conv block, N=128 half. MODE 1: LSTM step (sync-free fused
// epilogue; finalout => t=9 writes fp32 h,c into d_out); MODE 0: gates =
// conv + bias, written gate-minor fp32 (xg producer).
// 8 warps as 2(M) x 4(N); warp tile 32x32; 32 fp32 accumulators per thread.
// A via cp.async (zero-fill halo); B frags via LDG.128 pairs. Target 64 regs.
// ---------------------------------------------------------------------------
template <int MODE>
__global__ void __launch_bounds__(256, 4)
mm_conv(const __half* __restrict__ in, const uint4* __restrict__ wt,
        const float* __restrict__ xg_or_bias, float* __restrict__ gout,
        float* __restrict__ cbuf, __half* __restrict__ hout,
        __half* __restrict__ outseq, float* __restrict__ finalout, int tstep) {
    extern __shared__ float smf[];
    unsigned sbase = smem_u32(smf);
    int tid = threadIdx.x;
    int wid = tid >> 5, lane = tid & 31;
    int g = lane >> 2, tg = lane & 3;
    int mw = wid >> 2, nw = wid & 3;
    int m_base = mw * 32;
    int img = blockIdx.y;
    int y0 = blockIdx.x >> 1;                  // image row handled by block
    int half = blockIdx.x & 1;                 // channel half (f 0-31 / 32-63)
    const __half* inb = in + (size_t)img * (NPIX * FDIM);
    int fglob = half * 32 + nw * 8 + 2 * tg;   // this thread's channel (even)
    // per-lane invariant part of ldmatrix addresses (words)
    int lanepart = (lane & 15) * 36 + ((lane >> 4) << 2);

    // ---- fill persistent A via cp.async: [3][66 pos][32 words], halo=0 ----
    for (int i = tid; i < 1584; i += 256) {
        int dyi = i / 528;
        int rem = i - dyi * 528;
        int xx = rem >> 3;                         // 0..65 (pos)
        int w4 = (rem & 7) << 2;                   // word offset in row
        int y = y0 + dyi - 1;
        int x = xx - 1;
        bool ok = ((unsigned)y < 64u) && ((unsigned)x < 64u);
        const __half* src = ok ? inb + (size_t)(((y << 6) + x) * 64 + (w4 << 1))
                               : inb;
        unsigned daddr = sbase + (unsigned)(dyi * 2376 + xx * 36 + w4) * 4;
        int sz = ok ? 16 : 0;
        asm volatile("cp.async.ca.shared.global [%0], [%1], 16, %2;"
                     :: "r"(daddr), "l"(src), "r"(sz));
    }
    asm volatile("cp.async.commit_group;");

    float acc[2][4][4];
#pragma unroll
    for (int mi = 0; mi < 2; ++mi)
#pragma unroll
        for (int ni = 0; ni < 4; ++ni)
#pragma unroll
            for (int r = 0; r < 4; ++r) acc[mi][ni][r] = 0.0f;

    asm volatile("cp.async.wait_group 0;");
    __syncthreads();                               // A ready; only barrier

    // warp's B base: + (s*4+kf)*256 per stage/kf
    const uint4* bwarp = wt + half * 9216 + (nw << 6) + (lane << 1);

#pragma unroll
    for (int s = 0; s < 9; ++s) {
        const int qy = s / 3;                      // dy+1 (compile-time)
        const int dx = s - 3 * qy - 1;
        int rowbase = qy * 2376 + (m_base + dx + 1) * 36 + lanepart;
        unsigned aaddr0 = sbase + (unsigned)rowbase * 4;
        unsigned aaddr1 = aaddr0 + 16 * 36 * 4;

#pragma unroll
        for (int kf = 0; kf < 4; ++kf) {
            const uint4* bs = bwarp + (s * 4 + kf) * 256;
            uint4 p0 = bs[0];
            uint4 p1 = bs[1];
            unsigned a0[4], a1[4];
            ldm_x4(a0, aaddr0 + (unsigned)(kf * 32));
            ldm_x4(a1, aaddr1 + (unsigned)(kf * 32));
            MMA_F16(acc[0][0], a0, p0.x, p0.y);
            MMA_F16(acc[1][0], a1, p0.x, p0.y);
            MMA_F16(acc[0][1], a0, p0.z, p0.w);
            MMA_F16(acc[1][1], a1, p0.z, p0.w);
            MMA_F16(acc[0][2], a0, p1.x, p1.y);
            MMA_F16(acc[1][2], a1, p1.x, p1.y);
            MMA_F16(acc[0][3], a0, p1.z, p1.w);
            MMA_F16(acc[1][3], a1, p1.z, p1.w);
        }
    }

    // ---- epilogue (no smem, no barriers: thread owns i,f,g,o) ------------
    if (MODE == 0) {
        // gates -> gout gate-minor [pix][f][4], + bias
        float bi[2][4];
#pragma unroll
        for (int j = 0; j < 2; ++j)
#pragma unroll
            for (int k = 0; k < 4; ++k)
                bi[j][k] = xg_or_bias[k * 64 + fglob + j];
#pragma unroll
        for (int mi = 0; mi < 2; ++mi)
#pragma unroll
            for (int rh = 0; rh < 2; ++rh) {
                int pix = y0 * 64 + m_base + mi * 16 + rh * 8 + g;
                float* ob = gout + ((size_t)img * NPIX + pix) * 256 + (size_t)fglob * 4;
                int cb = rh * 2;
#pragma unroll
                for (int j = 0; j < 2; ++j) {
                    float4 v = make_float4(acc[mi][0][cb + j] + bi[j][0],
                                           acc[mi][1][cb + j] + bi[j][1],
                                           acc[mi][2][cb + j] + bi[j][2],
                                           acc[mi][3][cb + j] + bi[j][3]);
                    *(float4*)(ob + j * 4) = v;
                }
            }
    } else {
#pragma unroll
        for (int mi = 0; mi < 2; ++mi)
#pragma unroll
            for (int rh = 0; rh < 2; ++rh) {
                int pix = y0 * 64 + m_base + mi * 16 + rh * 8 + g;
                const float4* xq = (const float4*)(xg_or_bias +
                    ((size_t)(img * 10 + tstep) * NPIX + pix) * 256 + (size_t)fglob * 4);
                float4 q0 = xq[0], q1 = xq[1];          // (i,f,g,o) for ch, ch+1
                size_t hoff = ((size_t)img * NPIX + pix) * 64 + fglob;
                float2 co = *(const float2*)(cbuf + hoff);
                int cb = rh * 2;
                float cn0 = hsig(acc[mi][1][cb] + q0.y) * co.x
                          + hsig(acc[mi][0][cb] + q0.x) * tanhf(acc[mi][2][cb] + q0.z);
                float cn1 = hsig(acc[mi][1][cb + 1] + q1.y) * co.y
                          + hsig(acc[mi][0][cb + 1] + q1.x) * tanhf(acc[mi][2][cb + 1] + q1.z);
                float hn0 = hsig(acc[mi][3][cb] + q0.w) * tanhf(cn0);
                float hn1 = hsig(acc[mi][3][cb + 1] + q1.w) * tanhf(cn1);
                __half2 hh = __floats2half2_rn(hn0, hn1);
                if (finalout) {                      // t=9: write fp32 h,c to d_out
                    *(float2*)(finalout + hoff)       = make_float2(hn0, hn1);
                    *(float2*)(finalout + SEG + hoff) = make_float2(cn0, cn1);
                } else {
                    *(float2*)(cbuf + hoff) = make_float2(cn0, cn1);
                    *(__half2*)(hout + hoff) = hh;
                }
                if (outseq)
                    *(__half2*)(outseq + ((size_t)(img * 10 + tstep) * NPIX + pix) * 64
                                + fglob) = hh;
            }
    }
}

// ---------------------------------------------------------------------------
extern "C" void kernel_launch(void* const* d_in, const int* in_sizes, int n_in,
                              void* d_out, int out_size) {
    const float* x   = (const float*)d_in[0];
    const float* Wx0 = (const float*)d_in[1];
    const float* Wh0 = (const float*)d_in[2];
    const float* b0  = (const float*)d_in[3];
    const float* Wx1 = (const float*)d_in[4];
    const float* Wh1 = (const float*)d_in[5];
    const float* b1  = (const float*)d_in[6];
    float* out = (float*)d_out;

    float *xg0, *xg1, *cb;
    __half *out0, *hbase;
    uint4* wt;
    cudaGetSymbolAddress((void**)&xg0,   g_xg0);
    cudaGetSymbolAddress((void**)&xg1,   g_xg1);
    cudaGetSymbolAddress((void**)&out0,  g_out0H);
    cudaGetSymbolAddress((void**)&hbase, g_hH);
    cudaGetSymbolAddress((void**)&cb,    g_c);
    cudaGetSymbolAddress((void**)&wt,    g_wtH);
    __half* hb[2] = { hbase, hbase + SEG };

    cudaFuncSetAttribute(mm_conv<1>, cudaFuncAttributeMaxDynamicSharedMemorySize, SMEM_BYTES);
    cudaFuncSetAttribute(mm_conv<0>, cudaFuncAttributeMaxDynamicSharedMemorySize, SMEM_BYTES);

    // fp16 fragment-order gate-interleaved weights: [0]=Wh0, [1]=Wx1, [2]=Wh1
    prep_w<<<432, 256>>>(Wh0, Wx1, Wh1);

    // Layer-0 input conv (exact fp32, gate-minor xg)
    conv_l0<<<dim3(16, 80), 256>>>(x, Wx0, b0, xg0);

    // Layer 0: t=0 exact init, t=1..8 steps, t=9 step writes d_out layer 0
    lstm_init<<<2048, 256>>>(xg0, cb, hb[1], out0);
    for (int t = 1; t < 9; ++t)
        mm_conv<1><<<dim3(128, 8), 256, SMEM_BYTES>>>(
            hb[t & 1], wt, xg0, nullptr, cb, hb[(t + 1) & 1], out0, nullptr, t);
    mm_conv<1><<<dim3(128, 8), 256, SMEM_BYTES>>>(
        hb[1], wt, xg0, nullptr, cb, nullptr, out0, out, 9);

    // Layer-1 batched input conv over 80 images (produces gate-minor xg1)
    mm_conv<0><<<dim3(128, 80), 256, SMEM_BYTES>>>(
        out0, wt + 18432, b1, xg1, nullptr, nullptr, nullptr, nullptr, 0);

    // Layer 1: t=0 exact init, t=1..8 steps, t=9 step writes d_out layer 1
    lstm_init<<<2048, 256>>>(xg1, cb, hb[1], nullptr);
    for (int t = 1; t < 9; ++t)
        mm_conv<1><<<dim3(128, 8), 256, SMEM_BYTES>>>(
            hb[t & 1], wt + 2 * 18432, xg1, nullptr, cb, hb[(t + 1) & 1], nullptr,
            nullptr, t);
    mm_conv<1><<<dim3(128, 8), 256, SMEM_BYTES>>>(
        hb[1], wt + 2 * 18432, xg1, nullptr, cb, nullptr, nullptr, out + 2 * SEG, 9);

    (void)in_sizes; (void)n_in; (void)out_size;
}

// round 15
// speedup vs baseline: 1.4022x; 1.4022x over previous
#include <cuda_runtime.h>
#include <cuda_fp16.h>
#include <math.h>
#include <stdint.h>

// ---------------------------------------------------------------------------
// B=8, T=10, H=W=64, Cin=1, F=64, 4F=256, k=3x3 SAME.
// Output: [2][2][8][64][64][64] fp32.
// fp16 mma.sync (m16n8k16, fp32 accum) implicit-GEMM conv.
// Per block: M=64 positions (one image row) x N=128 (one channel-half, gates
// interleaved), K=576 as 9 taps. Warp tile 32x32 -> 32 accums -> 3 blocks/SM
// (80 regs, no spill: R14 showed the 64-reg squeeze spills via L1).
// h/out0 stored fp16 (bit-identical path), A-fill via cp.async w/ zero-fill
// halo, B frags via LDG.128 pairs from gmem (L2-broadcast). Mainloop
// barrier-free. t=0 exact elementwise init; t=9 writes h,c into d_out.
// ---------------------------------------------------------------------------

#define HW    64
#define FDIM  64
#define C4    256
#define NPIX  4096
#define SEG   2097152            // 8*4096*64

__device__ float  g_xg0[10 * 8 * NPIX * C4];   // gate-minor: [timg][pix][f][4]
__device__ float  g_xg1[10 * 8 * NPIX * C4];
__device__ __half g_out0H[10 * 8 * NPIX * FDIM];
__device__ __half g_hH[2][SEG];
__device__ float  g_c[SEG];
// fp16 fragment-ordered weights, uint4-paired:
// uint4[which(3)][half(2)][s(9)][kf(4)][nw(4)][lane(32)][pair(2)]
__device__ uint4 g_wtH[3 * 18432];

__device__ __forceinline__ float hsig(float x) {
    return fminf(fmaxf(0.2f * x + 0.5f, 0.0f), 1.0f);
}
__device__ __forceinline__ unsigned smem_u32(const void* p) {
    unsigned r;
    asm("{ .reg .u64 t; cvta.to.shared.u64 t, %1; cvt.u32.u64 %0, t; }"
        : "=r"(r) : "l"(p));
    return r;
}
__device__ __forceinline__ void ldm_x4(unsigned* a, unsigned addr) {
    asm volatile("ldmatrix.sync.aligned.m8n8.x4.shared.b16 {%0,%1,%2,%3}, [%4];"
        : "=r"(a[0]), "=r"(a[1]), "=r"(a[2]), "=r"(a[3]) : "r"(addr));
}

#define MMA_F16(c, a, bx, by)                                                  \
    asm volatile("mma.sync.aligned.m16n8k16.row.col.f32.f16.f16.f32 "          \
        "{%0,%1,%2,%3}, {%4,%5,%6,%7}, {%8,%9}, {%0,%1,%2,%3};"                \
        : "+f"(c[0]), "+f"(c[1]), "+f"(c[2]), "+f"(c[3])                       \
        : "r"(a[0]), "r"(a[1]), "r"(a[2]), "r"(a[3]), "r"(bx), "r"(by))

// smem: A fp16x2 words [3][66][36] = 7128 u32 (pos stride 36 words). 28512B.
#define SMEM_BYTES 28672

// ---------------------------------------------------------------------------
// t=0 LSTM step, exact (h_prev=0 -> gates = xg). xg is gate-minor [pix][f][4].
__global__ void lstm_init(const float* __restrict__ xg, float* __restrict__ cbuf,
                          __half* __restrict__ hout, __half* __restrict__ outseq) {
    int i = blockIdx.x * blockDim.x + threadIdx.x;     // float4 index in [pix][64]
    if (i >= SEG / 4) return;
    int f4 = (i & 15) << 2;                             // channel base
    int pixg = i >> 4;                                  // img*4096 + pix
    int img = pixg >> 12;
    const float4* xp = (const float4*)(xg +
        ((size_t)(img * 10) * NPIX + (pixg & 4095)) * 256 + (size_t)f4 * 4);
    float4 cn, hn;
    {
        float4 q0 = xp[0], q1 = xp[1], q2 = xp[2], q3 = xp[3];  // (i,f,g,o) x 4 ch
        cn.x = hsig(q0.x) * tanhf(q0.z);
        cn.y = hsig(q1.x) * tanhf(q1.z);
        cn.z = hsig(q2.x) * tanhf(q2.z);
        cn.w = hsig(q3.x) * tanhf(q3.z);
        hn.x = hsig(q0.w) * tanhf(cn.x);
        hn.y = hsig(q1.w) * tanhf(cn.y);
        hn.z = hsig(q2.w) * tanhf(cn.z);
        hn.w = hsig(q3.w) * tanhf(cn.w);
    }
    *(float4*)(cbuf + (size_t)i * 4) = cn;
    __half2 h01 = __floats2half2_rn(hn.x, hn.y);
    __half2 h23 = __floats2half2_rn(hn.z, hn.w);
    *(__half2*)(hout + (size_t)i * 4)     = h01;
    *(__half2*)(hout + (size_t)i * 4 + 2) = h23;
    if (outseq) {
        __half* op = outseq + ((size_t)(img * 10) * NPIX + (pixg & 4095)) * 64 + f4;
        *(__half2*)(op)     = h01;
        *(__half2*)(op + 2) = h23;
    }
}

// Weights -> fp16 B-fragment order, uint4-paired:
// uint2 j decomposition: inner=j&1, pair=(j>>1)&1, lane=(j>>2)&31, nw=(j>>7)&3,
// kf=(j>>9)&3, s=j>>11; ni = pair*2+inner (= gate), tg=lane&3, gg=lane>>2.
// col = ni*64 + half*32 + nw*8 + gg; k0 = s*64 + kf*16 + 2*tg.
// value = { pack(W[k0][col],W[k0+1][col]), pack(W[k0+8][col],W[k0+9][col]) }.
__global__ void prep_w(const float* __restrict__ w0, const float* __restrict__ w1,
                       const float* __restrict__ w2) {
    int idx = blockIdx.x * 256 + threadIdx.x;      // uint2 index
    if (idx >= 3 * 36864) return;
    int which = idx / 36864;
    int rem   = idx - which * 36864;
    int half = rem / 18432;
    int j    = rem - half * 18432;
    int inner = j & 1;
    int pair  = (j >> 1) & 1;
    int lane  = (j >> 2) & 31;
    int nw    = (j >> 7) & 3;
    int kf    = (j >> 9) & 3;
    int s     = j >> 11;
    int ni = pair * 2 + inner;
    int tg = lane & 3, gg = lane >> 2;
    const float* src = (which == 0) ? w0 : (which == 1) ? w1 : w2;
    int k0  = s * 64 + kf * 16 + 2 * tg;
    int col = ni * 64 + half * 32 + nw * 8 + gg;
    __half2 b0 = __floats2half2_rn(src[(size_t)k0 * 256 + col],
                                   src[(size_t)(k0 + 1) * 256 + col]);
    __half2 b1 = __floats2half2_rn(src[(size_t)(k0 + 8) * 256 + col],
                                   src[(size_t)(k0 + 9) * 256 + col]);
    uint2 v;
    v.x = *(unsigned*)&b0;
    v.y = *(unsigned*)&b1;
    ((uint2*)g_wtH)[idx] = v;
}

// Layer-0 input conv (Cin=1), exact fp32, writes xg gate-minor:
// thread tid = source col (gate*64+f) -> stored at [pix][f*4 + gate].
__global__ void conv_l0(const float* __restrict__ x, const float* __restrict__ w,
                        const float* __restrict__ b, float* __restrict__ xg) {
    __shared__ float ps[18 * 18];
    __shared__ float ws[9 * C4];
    int img = blockIdx.y;
    int by0 = (blockIdx.x >> 2) * 16, bx0 = (blockIdx.x & 3) * 16;
    int tid = threadIdx.x;
    int perm = (tid & 63) * 4 + (tid >> 6);
    for (int i = tid; i < 324; i += 256) {
        int ly = i / 18, lx = i - ly * 18;
        int gy = by0 + ly - 1, gx = bx0 + lx - 1;
        float v = 0.0f;
        if (gy >= 0 && gy < HW && gx >= 0 && gx < HW)
            v = x[(size_t)img * NPIX + gy * HW + gx];
        ps[i] = v;
    }
    for (int i = tid; i < 9 * C4; i += 256) ws[i] = w[i];
    __syncthreads();
    float wr[9];
#pragma unroll
    for (int tp = 0; tp < 9; ++tp) wr[tp] = ws[tp * C4 + tid];
    float bv = b[tid];
    for (int p = 0; p < 256; ++p) {
        int py = p >> 4, px = p & 15;
        float a = bv;
#pragma unroll
        for (int tp = 0; tp < 9; ++tp) {
            int dy = tp / 3, dx = tp - 3 * dy;
            a += ps[(py + dy) * 18 + (px + dx)] * wr[tp];
        }
        xg[((size_t)img * NPIX + (by0 + py) * HW + (bx0 + px)) * C4 + perm] = a;
    }
}

// ---------------------------------------------------------------------------
// fp16 mma.sync conv block, N=128 half. MODE 1: LSTM step (sync-free fused
// epilogue; finalout => t=9 writes fp32 h,c into d_out); MODE 0: gates =
// conv + bias, written gate-minor fp32 (xg producer).
// 8 warps as 2(M) x 4(N); warp tile 32x32; 32 fp32 accumulators per thread.
// A via cp.async (zero-fill halo); B frags via LDG.128 pairs. 3 blocks/SM.
// ---------------------------------------------------------------------------
template <int MODE>
__global__ void __launch_bounds__(256, 3)
mm_conv(const __half* __restrict__ in, const uint4* __restrict__ wt,
        const float* __restrict__ xg_or_bias, float* __restrict__ gout,
        float* __restrict__ cbuf, __half* __restrict__ hout,
        __half* __restrict__ outseq, float* __restrict__ finalout, int tstep) {
    extern __shared__ float smf[];
    unsigned sbase = smem_u32(smf);
    int tid = threadIdx.x;
    int wid = tid >> 5, lane = tid & 31;
    int g = lane >> 2, tg = lane & 3;
    int mw = wid >> 2, nw = wid & 3;
    int m_base = mw * 32;
    int img = blockIdx.y;
    int y0 = blockIdx.x >> 1;                  // image row handled by block
    int half = blockIdx.x & 1;                 // channel half (f 0-31 / 32-63)
    const __half* inb = in + (size_t)img * (NPIX * FDIM);
    int fglob = half * 32 + nw * 8 + 2 * tg;   // this thread's channel (even)
    // per-lane invariant part of ldmatrix addresses (words)
    int lanepart = (lane & 15) * 36 + ((lane >> 4) << 2);

    // ---- fill persistent A via cp.async: [3][66 pos][32 words], halo=0 ----
    for (int i = tid; i < 1584; i += 256) {
        int dyi = i / 528;
        int rem = i - dyi * 528;
        int xx = rem >> 3;                         // 0..65 (pos)
        int w4 = (rem & 7) << 2;                   // word offset in row
        int y = y0 + dyi - 1;
        int x = xx - 1;
        bool ok = ((unsigned)y < 64u) && ((unsigned)x < 64u);
        const __half* src = ok ? inb + (size_t)(((y << 6) + x) * 64 + (w4 << 1))
                               : inb;
        unsigned daddr = sbase + (unsigned)(dyi * 2376 + xx * 36 + w4) * 4;
        int sz = ok ? 16 : 0;
        asm volatile("cp.async.ca.shared.global [%0], [%1], 16, %2;"
                     :: "r"(daddr), "l"(src), "r"(sz));
    }
    asm volatile("cp.async.commit_group;");

    float acc[2][4][4];
#pragma unroll
    for (int mi = 0; mi < 2; ++mi)
#pragma unroll
        for (int ni = 0; ni < 4; ++ni)
#pragma unroll
            for (int r = 0; r < 4; ++r) acc[mi][ni][r] = 0.0f;

    asm volatile("cp.async.wait_group 0;");
    __syncthreads();                               // A ready; only barrier

    // warp's B base: + (s*4+kf)*256 per stage/kf
    const uint4* bwarp = wt + half * 9216 + (nw << 6) + (lane << 1);

#pragma unroll
    for (int s = 0; s < 9; ++s) {
        const int qy = s / 3;                      // dy+1 (compile-time)
        const int dx = s - 3 * qy - 1;
        int rowbase = qy * 2376 + (m_base + dx + 1) * 36 + lanepart;
        unsigned aaddr0 = sbase + (unsigned)rowbase * 4;
        unsigned aaddr1 = aaddr0 + 16 * 36 * 4;

#pragma unroll
        for (int kf = 0; kf < 4; ++kf) {
            const uint4* bs = bwarp + (s * 4 + kf) * 256;
            uint4 p0 = bs[0];
            uint4 p1 = bs[1];
            unsigned a0[4], a1[4];
            ldm_x4(a0, aaddr0 + (unsigned)(kf * 32));
            ldm_x4(a1, aaddr1 + (unsigned)(kf * 32));
            MMA_F16(acc[0][0], a0, p0.x, p0.y);
            MMA_F16(acc[1][0], a1, p0.x, p0.y);
            MMA_F16(acc[0][1], a0, p0.z, p0.w);
            MMA_F16(acc[1][1], a1, p0.z, p0.w);
            MMA_F16(acc[0][2], a0, p1.x, p1.y);
            MMA_F16(acc[1][2], a1, p1.x, p1.y);
            MMA_F16(acc[0][3], a0, p1.z, p1.w);
            MMA_F16(acc[1][3], a1, p1.z, p1.w);
        }
    }

    // ---- epilogue (no smem, no barriers: thread owns i,f,g,o) ------------
    if (MODE == 0) {
        // gates -> gout gate-minor [pix][f][4], + bias
        float bi[2][4];
#pragma unroll
        for (int j = 0; j < 2; ++j)
#pragma unroll
            for (int k = 0; k < 4; ++k)
                bi[j][k] = xg_or_bias[k * 64 + fglob + j];
#pragma unroll
        for (int mi = 0; mi < 2; ++mi)
#pragma unroll
            for (int rh = 0; rh < 2; ++rh) {
                int pix = y0 * 64 + m_base + mi * 16 + rh * 8 + g;
                float* ob = gout + ((size_t)img * NPIX + pix) * 256 + (size_t)fglob * 4;
                int cb = rh * 2;
#pragma unroll
                for (int j = 0; j < 2; ++j) {
                    float4 v = make_float4(acc[mi][0][cb + j] + bi[j][0],
                                           acc[mi][1][cb + j] + bi[j][1],
                                           acc[mi][2][cb + j] + bi[j][2],
                                           acc[mi][3][cb + j] + bi[j][3]);
                    *(float4*)(ob + j * 4) = v;
                }
            }
    } else {
#pragma unroll
        for (int mi = 0; mi < 2; ++mi)
#pragma unroll
            for (int rh = 0; rh < 2; ++rh) {
                int pix = y0 * 64 + m_base + mi * 16 + rh * 8 + g;
                const float4* xq = (const float4*)(xg_or_bias +
                    ((size_t)(img * 10 + tstep) * NPIX + pix) * 256 + (size_t)fglob * 4);
                float4 q0 = xq[0], q1 = xq[1];          // (i,f,g,o) for ch, ch+1
                size_t hoff = ((size_t)img * NPIX + pix) * 64 + fglob;
                float2 co = *(const float2*)(cbuf + hoff);
                int cb = rh * 2;
                float cn0 = hsig(acc[mi][1][cb] + q0.y) * co.x
                          + hsig(acc[mi][0][cb] + q0.x) * tanhf(acc[mi][2][cb] + q0.z);
                float cn1 = hsig(acc[mi][1][cb + 1] + q1.y) * co.y
                          + hsig(acc[mi][0][cb + 1] + q1.x) * tanhf(acc[mi][2][cb + 1] + q1.z);
                float hn0 = hsig(acc[mi][3][cb] + q0.w) * tanhf(cn0);
                float hn1 = hsig(acc[mi][3][cb + 1] + q1.w) * tanhf(cn1);
                __half2 hh = __floats2half2_rn(hn0, hn1);
                if (finalout) {                      // t=9: write fp32 h,c to d_out
                    *(float2*)(finalout + hoff)       = make_float2(hn0, hn1);
                    *(float2*)(finalout + SEG + hoff) = make_float2(cn0, cn1);
                } else {
                    *(float2*)(cbuf + hoff) = make_float2(cn0, cn1);
                    *(__half2*)(hout + hoff) = hh;
                }
                if (outseq)
                    *(__half2*)(outseq + ((size_t)(img * 10 + tstep) * NPIX + pix) * 64
                                + fglob) = hh;
            }
    }
}

// ---------------------------------------------------------------------------
extern "C" void kernel_launch(void* const* d_in, const int* in_sizes, int n_in,
                              void* d_out, int out_size) {
    const float* x   = (const float*)d_in[0];
    const float* Wx0 = (const float*)d_in[1];
    const float* Wh0 = (const float*)d_in[2];
    const float* b0  = (const float*)d_in[3];
    const float* Wx1 = (const float*)d_in[4];
    const float* Wh1 = (const float*)d_in[5];
    const float* b1  = (const float*)d_in[6];
    float* out = (float*)d_out;

    float *xg0, *xg1, *cb;
    __half *out0, *hbase;
    uint4* wt;
    cudaGetSymbolAddress((void**)&xg0,   g_xg0);
    cudaGetSymbolAddress((void**)&xg1,   g_xg1);
    cudaGetSymbolAddress((void**)&out0,  g_out0H);
    cudaGetSymbolAddress((void**)&hbase, g_hH);
    cudaGetSymbolAddress((void**)&cb,    g_c);
    cudaGetSymbolAddress((void**)&wt,    g_wtH);
    __half* hb[2] = { hbase, hbase + SEG };

    cudaFuncSetAttribute(mm_conv<1>, cudaFuncAttributeMaxDynamicSharedMemorySize, SMEM_BYTES);
    cudaFuncSetAttribute(mm_conv<0>, cudaFuncAttributeMaxDynamicSharedMemorySize, SMEM_BYTES);

    // fp16 fragment-order gate-interleaved weights: [0]=Wh0, [1]=Wx1, [2]=Wh1
    prep_w<<<432, 256>>>(Wh0, Wx1, Wh1);

    // Layer-0 input conv (exact fp32, gate-minor xg)
    conv_l0<<<dim3(16, 80), 256>>>(x, Wx0, b0, xg0);

    // Layer 0: t=0 exact init, t=1..8 steps, t=9 step writes d_out layer 0
    lstm_init<<<2048, 256>>>(xg0, cb, hb[1], out0);
    for (int t = 1; t < 9; ++t)
        mm_conv<1><<<dim3(128, 8), 256, SMEM_BYTES>>>(
            hb[t & 1], wt, xg0, nullptr, cb, hb[(t + 1) & 1], out0, nullptr, t);
    mm_conv<1><<<dim3(128, 8), 256, SMEM_BYTES>>>(
        hb[1], wt, xg0, nullptr, cb, nullptr, out0, out, 9);

    // Layer-1 batched input conv over 80 images (produces gate-minor xg1)
    mm_conv<0><<<dim3(128, 80), 256, SMEM_BYTES>>>(
        out0, wt + 18432, b1, xg1, nullptr, nullptr, nullptr, nullptr, 0);

    // Layer 1: t=0 exact init, t=1..8 steps, t=9 step writes d_out layer 1
    lstm_init<<<2048, 256>>>(xg1, cb, hb[1], nullptr);
    for (int t = 1; t < 9; ++t)
        mm_conv<1><<<dim3(128, 8), 256, SMEM_BYTES>>>(
            hb[t & 1], wt + 2 * 18432, xg1, nullptr, cb, hb[(t + 1) & 1], nullptr,
            nullptr, t);
    mm_conv<1><<<dim3(128, 8), 256, SMEM_BYTES>>>(
        hb[1], wt + 2 * 18432, xg1, nullptr, cb, nullptr, nullptr, out + 2 * SEG, 9);

    (void)in_sizes; (void)n_in; (void)out_size;
}